// round 17
// baseline (speedup 1.0000x reference)
#include <cuda_runtime.h>
#include <cuda_fp16.h>
#include <cstdint>

#define N_NODES 100000
#define N_EDGES 1600000
#define DIM     128

// ---------------- scratch (device globals; no allocation in kernel_launch) ---
__device__ int   g_deg[N_NODES];
__device__ int   g_off[N_NODES + 1];
__device__ int   g_cur[N_NODES];
__device__ int   g_csr[N_EDGES];
__device__ float g_invdeg[N_NODES];
// unified fp16 activation planes (GEMM A operands AND gather sources)
__device__ __half g_f16[(long long)N_NODES * DIM];   // features
__device__ __half g_g16[(long long)N_NODES * DIM];   // neighbor means (per layer)
__device__ __half g_h1 [(long long)N_NODES * DIM];   // layer-1 output

// ---------------- prep: features -> fp16 plane + zero deg --------------------
__global__ void prep_kernel(const float* __restrict__ in, int n4) {
    int i = blockIdx.x * blockDim.x + threadIdx.x;
    if (i < N_NODES) g_deg[i] = 0;            // runs before count_deg (stream order)
    if (i >= n4) return;
    float4 v = *(const float4*)(in + (long long)i * 4);
    *(__half2*)(g_f16 + (long long)i * 4)     = __floats2half2_rn(v.x, v.y);
    *(__half2*)(g_f16 + (long long)i * 4 + 2) = __floats2half2_rn(v.z, v.w);
}

// ---------------- CSR build (2 edges per thread) -----------------------------
__global__ void count_deg_kernel(const int* __restrict__ dst) {
    int i = blockIdx.x * blockDim.x + threadIdx.x;
    if (i * 2 < N_EDGES) {
        int2 d = *(const int2*)(dst + i * 2);
        atomicAdd(&g_deg[d.x], 1);
        atomicAdd(&g_deg[d.y], 1);
    }
}
// fused scan: block b direct-sums deg[0..b*256) for its base, then local scan
__global__ void scanoff_kernel() {
    __shared__ int red[256];
    __shared__ int sh[256];
    int b = blockIdx.x, t = threadIdx.x;
    int i = b * 256 + t;
    int lim = b * 256;
    int p = 0;
    for (int j = t; j < lim; j += 256) p += g_deg[j];
    red[t] = p;
    int dg = (i < N_NODES) ? g_deg[i] : 0;
    sh[t] = dg;
    __syncthreads();
    for (int d = 128; d > 0; d >>= 1) {
        if (t < d) red[t] += red[t + d];
        __syncthreads();
    }
    int base = red[0];
    for (int d = 1; d < 256; d <<= 1) {
        int v = (t >= d) ? sh[t - d] : 0;
        __syncthreads();
        sh[t] += v;
        __syncthreads();
    }
    if (i < N_NODES) {
        int off = base + sh[t] - dg;
        g_off[i] = off;
        g_cur[i] = off;
        g_invdeg[i] = 1.0f / (float)(dg > 0 ? dg : 1);
        if (i == N_NODES - 1) g_off[N_NODES] = off + dg;
    }
}
__global__ void build_csr_kernel(const int* __restrict__ src,
                                 const int* __restrict__ dst) {
    int i = blockIdx.x * blockDim.x + threadIdx.x;
    if (i * 2 < N_EDGES) {
        int2 s = *(const int2*)(src + i * 2);
        int2 d = *(const int2*)(dst + i * 2);
        int p0 = atomicAdd(&g_cur[d.x], 1);
        g_csr[p0] = s.x;
        int p1 = atomicAdd(&g_cur[d.y], 1);
        g_csr[p1] = s.y;
    }
}

// ---------------- gather-side mean aggregation (warp per node, fp16) ---------
__global__ void gather_mean_f16_kernel(const __half* __restrict__ hsrc) {
    int warp = (blockIdx.x * blockDim.x + threadIdx.x) >> 5;
    if (warp >= N_NODES) return;
    int lane = threadIdx.x & 31;
    int s0 = g_off[warp];
    int s1 = g_off[warp + 1];
    float4 acc = make_float4(0.f, 0.f, 0.f, 0.f);

    auto addRow = [&](int node) {
        uint2 raw = *(const uint2*)(hsrc + (long long)node * DIM + lane * 4);
        float2 f0 = __half22float2(*(__half2*)&raw.x);
        float2 f1 = __half22float2(*(__half2*)&raw.y);
        acc.x += f0.x; acc.y += f0.y; acc.z += f1.x; acc.w += f1.y;
    };

    for (int e = s0; e < s1; e += 32) {
        int idx = (e + lane < s1) ? g_csr[e + lane] : 0;
        int cnt = s1 - e; if (cnt > 32) cnt = 32;
        int j = 0;
        for (; j + 8 <= cnt; j += 8) {
            int n0 = __shfl_sync(0xffffffffu, idx, j + 0);
            int n1 = __shfl_sync(0xffffffffu, idx, j + 1);
            int n2 = __shfl_sync(0xffffffffu, idx, j + 2);
            int n3 = __shfl_sync(0xffffffffu, idx, j + 3);
            int n4 = __shfl_sync(0xffffffffu, idx, j + 4);
            int n5 = __shfl_sync(0xffffffffu, idx, j + 5);
            int n6 = __shfl_sync(0xffffffffu, idx, j + 6);
            int n7 = __shfl_sync(0xffffffffu, idx, j + 7);
            uint2 r0 = *(const uint2*)(hsrc + (long long)n0 * DIM + lane * 4);
            uint2 r1 = *(const uint2*)(hsrc + (long long)n1 * DIM + lane * 4);
            uint2 r2 = *(const uint2*)(hsrc + (long long)n2 * DIM + lane * 4);
            uint2 r3 = *(const uint2*)(hsrc + (long long)n3 * DIM + lane * 4);
            uint2 r4 = *(const uint2*)(hsrc + (long long)n4 * DIM + lane * 4);
            uint2 r5 = *(const uint2*)(hsrc + (long long)n5 * DIM + lane * 4);
            uint2 r6 = *(const uint2*)(hsrc + (long long)n6 * DIM + lane * 4);
            uint2 r7 = *(const uint2*)(hsrc + (long long)n7 * DIM + lane * 4);
            uint2 rs[8] = {r0, r1, r2, r3, r4, r5, r6, r7};
#pragma unroll
            for (int q = 0; q < 8; q++) {
                float2 f0 = __half22float2(*(__half2*)&rs[q].x);
                float2 f1 = __half22float2(*(__half2*)&rs[q].y);
                acc.x += f0.x; acc.y += f0.y; acc.z += f1.x; acc.w += f1.y;
            }
        }
        for (; j < cnt; j++) addRow(__shfl_sync(0xffffffffu, idx, j));
    }
    float inv = g_invdeg[warp];
    long long o = (long long)warp * DIM + lane * 4;
    *(__half2*)(g_g16 + o)     = __floats2half2_rn(acc.x * inv, acc.y * inv);
    *(__half2*)(g_g16 + o + 2) = __floats2half2_rn(acc.z * inv, acc.w * inv);
}

// ---------------- persistent 16-warp mma.sync fp16 2-term GEMM ---------------
// D = A*Wh + A*Wl : single fp16 A plane, W split fp16 hi/lo. 512 thr, 4x4 warps.
// KC templated (128 for plain GEMM = fewer barriers; 64 for FUSEO smem budget).
// FUSEO: after computing the 128x128 tile, run tile @ W3 (128x64) in-kernel and
// write fp32 out directly (tile staged in smem, reusing the A-stage region).

#define MMA_F16(d, a, b)                                                      \
    asm volatile(                                                             \
        "mma.sync.aligned.m16n8k16.row.col.f32.f16.f16.f32 "                  \
        "{%0,%1,%2,%3}, {%4,%5,%6,%7}, {%8,%9}, {%0,%1,%2,%3};"               \
        : "+f"((d)[0]), "+f"((d)[1]), "+f"((d)[2]), "+f"((d)[3])              \
        : "r"((a)[0]), "r"((a)[1]), "r"((a)[2]), "r"((a)[3]),                 \
          "r"((b)[0]), "r"((b)[1]))

#define LDSM_X4(r0, r1, r2, r3, addr)                                         \
    asm volatile("ldmatrix.sync.aligned.m8n8.x4.shared.b16 {%0,%1,%2,%3}, [%4];" \
        : "=r"(r0), "=r"(r1), "=r"(r2), "=r"(r3) : "r"(addr))

#define CP_ASYNC16(dst, src)                                                  \
    asm volatile("cp.async.cg.shared.global [%0], [%1], 16;"                  \
                 :: "r"(dst), "l"(src))
#define CP_COMMIT()  asm volatile("cp.async.commit_group;" ::: "memory")
#define CP_WAIT(n)   asm volatile("cp.async.wait_group %0;" :: "n"(n) : "memory")

__device__ __forceinline__ uint32_t smem_u32(const void* p) {
    uint32_t a;
    asm("{ .reg .u64 t; cvta.to.shared.u64 t, %1; cvt.u32.u64 %0, t; }"
        : "=r"(a) : "l"(p));
    return a;
}

template <int KTOT, int NTILE, int KC, bool RELU, bool DUAL, bool WF16, bool FUSEO>
__global__ void __launch_bounds__(512, 1)
mma_gemm(const __half* __restrict__ A1, const __half* __restrict__ A2,
         const float* __restrict__ W1, const float* __restrict__ W2,
         const float* __restrict__ bias,
         const float* __restrict__ W3, const float* __restrict__ b3,
         __half* __restrict__ out16, float* __restrict__ outF, int M) {
    constexpr int NFRAG = NTILE / 32;        // n8 frags per warp (4)
    constexpr int MF    = 2;                 // m16 frags per warp (m32)
    constexpr int NCHUNK = KTOT / KC;        // even (2 or 4)
    constexpr int SA = KC + 8;
    constexpr int SB = KTOT + 8;
    constexpr int SH = 136;                  // fused tile / W_out stride
    constexpr int QPC = KC / 8;              // 16B quads per row per chunk
    constexpr int SEGS = 128 * QPC / 512;    // cp.async segs per thread
    constexpr int ABYTES = 128 * SA * 2;     // one A stage

    extern __shared__ __align__(16) __half smem[];
    __half* WH = smem;                       // [NTILE][SB]
    __half* WL = WH + NTILE * SB;

    const uint32_t sbase = smem_u32(smem);
    const int tid  = threadIdx.x;
    const int wid  = tid >> 5;
    const int lane = tid & 31;
    const int g    = lane >> 2;
    const int tq   = lane & 3;
    const int l8   = lane & 7;
    const int sel  = lane >> 3;

    // --- stage W transposed [n][k], split fp16 hi/lo (once per CTA) ---
    for (int idx = tid; idx < KTOT * NTILE; idx += 512) {
        int k = idx / NTILE, n = idx % NTILE;
        float w = (DUAL && k >= 128) ? W2[(k - 128) * NTILE + n]
                                     : W1[k * NTILE + n];
        __half h = __float2half_rn(w);
        WH[n * SB + k] = h;
        WL[n * SB + k] = __float2half_rn(w - __half2float(h));
    }

    const uint32_t whB = sbase;
    const uint32_t wlB = sbase + (uint32_t)(NTILE * SB) * 2;
    const uint32_t aB  = wlB + (uint32_t)(NTILE * SB) * 2;   // [2 stages][128][SA]
    const uint32_t woHB = aB + 2 * ABYTES;                   // FUSEO: [64][SH] x2
    const uint32_t woLB = woHB + (uint32_t)(64 * SH) * 2;

    if (FUSEO) {                             // stage W_out [128][64] -> [n][k]
        __half* WOH = smem + (woHB - sbase) / 2;
        __half* WOL = smem + (woLB - sbase) / 2;
        for (int idx = tid; idx < 128 * 64; idx += 512) {
            int k = idx / 64, n = idx % 64;
            float w = W3[k * 64 + n];
            __half h = __float2half_rn(w);
            WOH[n * SH + k] = h;
            WOL[n * SH + k] = __float2half_rn(w - __half2float(h));
        }
    }

    // --- async A staging: 128*QPC x 16B per chunk (single plane) ---
    auto stageA = [&](int row0, int c, int s) {
        const __half* pa; int kb;
        if (DUAL && c >= NCHUNK / 2) { pa = A2; kb = (c - NCHUNK / 2) * KC; }
        else                         { pa = A1; kb = c * KC; }
        const uint32_t aD = aB + (uint32_t)s * ABYTES;
#pragma unroll
        for (int it = 0; it < SEGS; it++) {
            int idx = tid + it * 512;
            int r = idx / QPC, q = idx % QPC;
            long long gr = row0 + r;
            if (gr > M - 1) gr = M - 1;          // clamp (rows >= M never stored)
            const __half* src = pa + gr * DIM + kb + q * 8;
            uint32_t dst = aD + (uint32_t)(r * SA + q * 8) * 2;
            CP_ASYNC16(dst, src);
        }
        CP_COMMIT();
    };

    // 4x4 warp grid: warp tile m32 x (NTILE/4)
    const int cw = wid & 3;
    const int rw = wid >> 2;
    const int n0 = cw * (NTILE / 4);
    const int wr0 = rw * 32;

    const int a_row_l = l8 + ((sel & 1) << 3);
    const int a_kadd  = (sel >> 1) << 3;
    const int b_row_l = l8 + ((sel >> 1) << 3);
    const int b_kadd  = (sel & 1) << 3;

    const int NT = (M + 127) >> 7;
    bool pf = false;                         // next tile's chunk0 prefetched?
    __syncthreads();   // W visible before first MMA

    for (int tile = blockIdx.x; tile < NT; tile += gridDim.x) {
        const int row0 = tile << 7;

        float acc[MF][NFRAG][4];
#pragma unroll
        for (int mf = 0; mf < MF; mf++)
#pragma unroll
            for (int nf = 0; nf < NFRAG; nf++)
#pragma unroll
                for (int j = 0; j < 4; j++) acc[mf][nf][j] = 0.f;

        if (!pf) stageA(row0, 0, 0);
        pf = false;

#pragma unroll 1
        for (int c = 0; c < NCHUNK; c++) {
            bool issued = true;
            if (c + 1 < NCHUNK) {
                stageA(row0, c + 1, (c + 1) & 1);
            } else if (!FUSEO) {             // cross-tile prefetch (aliases H)
                int ntile = tile + gridDim.x;
                if (ntile < NT) { stageA(ntile << 7, 0, 0); pf = true; }
                else issued = false;
            } else issued = false;
            if (issued) { CP_WAIT(1); } else { CP_WAIT(0); }
            __syncthreads();

            const uint32_t ast = (uint32_t)((c & 1)) * ABYTES;
#pragma unroll
            for (int ks = 0; ks < KC / 16; ks++) {
                const int k0 = ks * 16;
                const int kg = c * KC + k0;

                uint32_t af[MF][4];
#pragma unroll
                for (int mf = 0; mf < MF; mf++) {
                    uint32_t ao = (uint32_t)((wr0 + mf * 16 + a_row_l) * SA
                                             + k0 + a_kadd) * 2;
                    LDSM_X4(af[mf][0], af[mf][1], af[mf][2], af[mf][3],
                            aB + ast + ao);
                }
                uint32_t bh[NFRAG][2], bl[NFRAG][2];
#pragma unroll
                for (int nfp = 0; nfp < NFRAG / 2; nfp++) {
                    uint32_t bo = (uint32_t)((n0 + nfp * 16 + b_row_l) * SB
                                             + kg + b_kadd) * 2;
                    LDSM_X4(bh[2 * nfp][0], bh[2 * nfp][1],
                            bh[2 * nfp + 1][0], bh[2 * nfp + 1][1], whB + bo);
                    LDSM_X4(bl[2 * nfp][0], bl[2 * nfp][1],
                            bl[2 * nfp + 1][0], bl[2 * nfp + 1][1], wlB + bo);
                }
#pragma unroll
                for (int nf = 0; nf < NFRAG; nf++)
#pragma unroll
                    for (int mf = 0; mf < MF; mf++) {
                        MMA_F16(acc[mf][nf], af[mf], bh[nf]);
                        MMA_F16(acc[mf][nf], af[mf], bl[nf]);
                    }
            }
            __syncthreads();   // all reads done before next stage overwrites
        }

        // --- epilogue: bias (+relu); fp16 plane store or fused smem tile ---
        __half* Ht = smem + (aB - sbase) / 2;   // FUSEO: [128][SH] in A region
#pragma unroll
        for (int mf = 0; mf < MF; mf++) {
#pragma unroll
            for (int nf = 0; nf < NFRAG; nf++) {
                int col = n0 + nf * 8 + 2 * tq;
                int r = row0 + wr0 + mf * 16 + g;
                float b0 = __ldg(&bias[col]);
                float b1 = __ldg(&bias[col + 1]);
                float v[2][2] = {{acc[mf][nf][0] + b0, acc[mf][nf][1] + b1},
                                 {acc[mf][nf][2] + b0, acc[mf][nf][3] + b1}};
#pragma unroll
                for (int hrow = 0; hrow < 2; hrow++) {
                    int rr = r + hrow * 8;
                    float v0 = v[hrow][0], v1 = v[hrow][1];
                    if (RELU) { v0 = fmaxf(v0, 0.f); v1 = fmaxf(v1, 0.f); }
                    __half2 hv = __floats2half2_rn(v0, v1);
                    if (FUSEO) {
                        int lr = rr - row0;    // local tile row
                        *(__half2*)(Ht + lr * SH + col) = hv;
                    }
                    if (WF16 && rr < M)
                        *(__half2*)(out16 + (long long)rr * NTILE + col) = hv;
                }
            }
        }

        if (FUSEO) {
            __syncthreads();                  // tile complete in smem
            const int n0o = cw * 16;          // output warp cols (64/4)
            float acc2[MF][2][4];
#pragma unroll
            for (int mf = 0; mf < MF; mf++)
#pragma unroll
                for (int nf = 0; nf < 2; nf++)
#pragma unroll
                    for (int j = 0; j < 4; j++) acc2[mf][nf][j] = 0.f;

#pragma unroll
            for (int ks = 0; ks < 8; ks++) {
                const int k2 = ks * 16;
                uint32_t af2[MF][4];
#pragma unroll
                for (int mf = 0; mf < MF; mf++) {
                    uint32_t ao = (uint32_t)((wr0 + mf * 16 + a_row_l) * SH
                                             + k2 + a_kadd) * 2;
                    LDSM_X4(af2[mf][0], af2[mf][1], af2[mf][2], af2[mf][3],
                            aB + ao);
                }
                uint32_t bh2[2][2], bl2[2][2];
                uint32_t bo = (uint32_t)((n0o + b_row_l) * SH + k2 + b_kadd) * 2;
                LDSM_X4(bh2[0][0], bh2[0][1], bh2[1][0], bh2[1][1], woHB + bo);
                LDSM_X4(bl2[0][0], bl2[0][1], bl2[1][0], bl2[1][1], woLB + bo);
#pragma unroll
                for (int nf = 0; nf < 2; nf++)
#pragma unroll
                    for (int mf = 0; mf < MF; mf++) {
                        MMA_F16(acc2[mf][nf], af2[mf], bh2[nf]);
                        MMA_F16(acc2[mf][nf], af2[mf], bl2[nf]);
                    }
            }
#pragma unroll
            for (int mf = 0; mf < MF; mf++)
#pragma unroll
                for (int nf = 0; nf < 2; nf++) {
                    int col = n0o + nf * 8 + 2 * tq;
                    int r = row0 + wr0 + mf * 16 + g;
                    float b0 = __ldg(&b3[col]);
                    float b1 = __ldg(&b3[col + 1]);
#pragma unroll
                    for (int hrow = 0; hrow < 2; hrow++) {
                        int rr = r + hrow * 8;
                        if (rr >= M) continue;
                        *(float2*)(outF + (long long)rr * 64 + col) =
                            make_float2(acc2[mf][nf][hrow * 2 + 0] + b0,
                                        acc2[mf][nf][hrow * 2 + 1] + b1);
                    }
                }
            __syncthreads();                  // H reads done before next stageA
        }
    }
}

// ---------------- launch ------------------------------------------------------
extern "C" void kernel_launch(void* const* d_in, const int* in_sizes, int n_in,
                              void* d_out, int out_size) {
    (void)in_sizes; (void)n_in; (void)out_size;
    const float* features = (const float*)d_in[0];
    const int*   src      = (const int*)  d_in[1];
    const int*   dst      = (const int*)  d_in[2];
    const float* W_self1  = (const float*)d_in[3];
    const float* W_neigh1 = (const float*)d_in[4];
    const float* b1       = (const float*)d_in[5];
    const float* W_self2  = (const float*)d_in[6];
    const float* W_neigh2 = (const float*)d_in[7];
    const float* b2       = (const float*)d_in[8];
    const float* W_out    = (const float*)d_in[9];
    const float* b_out    = (const float*)d_in[10];
    float*       out      = (float*)d_out;

    __half *f16, *g16, *h1;
    cudaGetSymbolAddress((void**)&f16, g_f16);
    cudaGetSymbolAddress((void**)&g16, g_g16);
    cudaGetSymbolAddress((void**)&h1,  g_h1);

    // smem: GEMM-1 KC=128: W 135168 + 2x34816 = 204800
    //       GEMM-2 KC=64 fused: W 135168 + 2x18432 + 2x17408 = 206848
    const int SMEM_L1 = (2 * 128 * (256 + 8) + 2 * 128 * 136) * 2;               // 204800
    const int SMEM_L2 = (2 * 128 * (256 + 8) + 2 * 128 * 72 + 2 * 64 * 136) * 2; // 206848
    cudaFuncSetAttribute(mma_gemm<256, 128, 128, true, true, true, false>,
                         cudaFuncAttributeMaxDynamicSharedMemorySize, SMEM_L1);
    cudaFuncSetAttribute(mma_gemm<256, 128, 64, true, true, false, true>,
                         cudaFuncAttributeMaxDynamicSharedMemorySize, SMEM_L2);

    const int E2 = (N_EDGES / 2 + 255) / 256;      // 3125 (2 edges/thread)
    const int NB = (N_NODES + 255) / 256;          // 391
    const int GB = (N_NODES * 32 + 255) / 256;     // 12500 (warp per node)
    const int CB = (N_NODES * DIM / 4 + 255) / 256;
    const int PG = 148;

    // 1-4) feature fp16 plane (+deg zeroing) + CSR build
    prep_kernel<<<CB, 256>>>(features, N_NODES * DIM / 4);
    count_deg_kernel<<<E2, 256>>>(dst);
    scanoff_kernel<<<NB, 256>>>();
    build_csr_kernel<<<E2, 256>>>(src, dst);

    // 5-6) layer 1: gather(features) + dual GEMM (KC=128) -> h1 (fp16 plane)
    gather_mean_f16_kernel<<<GB, 256>>>(f16);
    mma_gemm<256, 128, 128, true, true, true, false><<<PG, 512, SMEM_L1>>>(
        f16, g16, W_self1, W_neigh1, b1, nullptr, nullptr, h1, nullptr, N_NODES);

    // 7-8) layer 2: gather(h1) + dual GEMM (KC=64) with FUSED output projection
    gather_mean_f16_kernel<<<GB, 256>>>(h1);
    mma_gemm<256, 128, 64, true, true, false, true><<<PG, 512, SMEM_L2>>>(
        h1, g16, W_self2, W_neigh2, b2, W_out, b_out, nullptr, out, N_NODES);
}